// round 1
// baseline (speedup 1.0000x reference)
#include <cuda_runtime.h>
#include <math.h>

#define BN   8
#define CIN  32
#define COUT 32
#define HW   384
#define AUX  128
#define HID  256
#define MODOUT (COUT*CIN*9)   // 9216

// Scratch (allocation-free rule: __device__ globals)
__device__ float g_wmod[BN * MODOUT];   // layout [n][ci][k][co]  (co minor!)
__device__ float g_bias[BN * COUT];

// ---------------------------------------------------------------------------
// Kernel 1: modulation MLP + bias MLP.
// grid = (8, 13): y=0..11 compute 768 mod outputs each, y=12 computes bias.
// ---------------------------------------------------------------------------
__global__ void mlp_kernel(const float* __restrict__ y,
                           const float* __restrict__ weight,
                           const float* __restrict__ fc_w1, const float* __restrict__ fc_b1,
                           const float* __restrict__ fc_a_p,
                           const float* __restrict__ fc_w2, const float* __restrict__ fc_b2,
                           const float* __restrict__ b_w1, const float* __restrict__ b_b1,
                           const float* __restrict__ b_a_p,
                           const float* __restrict__ b_w2, const float* __restrict__ b_b2)
{
    __shared__ float y_s[AUX];
    __shared__ float h_s[HID];
    const int n = blockIdx.x;
    const int t = threadIdx.x;

    if (t < AUX) y_s[t] = y[n*AUX + t];
    __syncthreads();

    if (blockIdx.y < 12) {
        // ---- modulation branch ----
        const float a = *fc_a_p;
        float h = fc_b1[t];
        #pragma unroll 4
        for (int i = 0; i < AUX; i++) h = fmaf(y_s[i], fc_w1[i*HID + t], h);
        h_s[t] = (h >= 0.f) ? h : a*h;
        __syncthreads();

        const int j0 = blockIdx.y * 768 + t;
        #pragma unroll
        for (int q = 0; q < 3; q++) {
            const int j = j0 + q*256;          // j = co*288 + ci*9 + k
            float m = fc_b2[j];
            #pragma unroll 4
            for (int hh = 0; hh < HID; hh++)
                m = fmaf(h_s[hh], fc_w2[hh*MODOUT + j], m);
            const float sg = 1.f / (1.f + expf(-m));
            const float wm = sg * weight[j];
            const int co = j / 288;
            const int r  = j - co*288;         // ci*9 + k
            g_wmod[n*MODOUT + r*32 + co] = wm; // transpose to co-minor
        }
    } else {
        // ---- bias branch ----
        const float a = *b_a_p;
        float h = b_b1[t];
        #pragma unroll 4
        for (int i = 0; i < AUX; i++) h = fmaf(y_s[i], b_w1[i*HID + t], h);
        h_s[t] = (h >= 0.f) ? h : a*h;
        __syncthreads();
        if (t < COUT) {
            float bsum = b_b2[t];
            #pragma unroll 4
            for (int hh = 0; hh < HID; hh++)
                bsum = fmaf(h_s[hh], b_w2[hh*COUT + t], bsum);
            g_bias[n*COUT + t] = bsum;
        }
    }
}

// ---------------------------------------------------------------------------
// Kernel 2: per-sample direct 3x3 conv, pad 1.
// Block: one sample, all 32 couts, 16x16 output tile.
// smem: weights [ci][k][co] 9216 f + input tile [ci][18][18] 10368 f = 78336 B.
// Thread: 2 couts x 4x4 spatial micro-tile (32 accumulators).
// ---------------------------------------------------------------------------
#define CONV_SMEM_BYTES ((9216 + 10368) * 4)

__global__ __launch_bounds__(256, 2)
void conv_kernel(const float* __restrict__ x, float* __restrict__ out)
{
    extern __shared__ float smem[];
    float* w_s = smem;            // 9216  floats: (ci*9+k)*32 + co
    float* x_s = smem + 9216;     // 10368 floats: ci*324 + ly*18 + lx

    const int n  = blockIdx.z;
    const int ty = blockIdx.y, tx = blockIdx.x;
    const int tid = threadIdx.x;

    // load per-sample weights (coalesced GMEM, conflict-free STS)
    const float* wsrc = g_wmod + n*MODOUT;
    #pragma unroll
    for (int i = tid; i < MODOUT; i += 256) w_s[i] = wsrc[i];

    // load input halo tile with zero padding
    const float* xn = x + (size_t)n * CIN * HW * HW;
    const int y0 = ty*16 - 1, x0 = tx*16 - 1;
    for (int i = tid; i < CIN*18*18; i += 256) {
        const int ci = i / 324;
        const int r  = i - ci*324;
        const int ly = r / 18, lx = r - ly*18;
        const int gy = y0 + ly, gx = x0 + lx;
        float v = 0.f;
        if ((unsigned)gy < HW && (unsigned)gx < HW)
            v = xn[(ci*HW + gy)*HW + gx];
        x_s[i] = v;
    }
    __syncthreads();

    const int cop = tid & 15;          // cout pair index -> couts {2cop, 2cop+1}
    const int s   = tid >> 4;          // spatial micro-tile 0..15
    const int sy  = (s >> 2) * 4;
    const int sx  = (s & 3) * 4;

    float acc0[16], acc1[16];
    #pragma unroll
    for (int i = 0; i < 16; i++) { acc0[i] = 0.f; acc1[i] = 0.f; }

    #pragma unroll 1
    for (int ci = 0; ci < CIN; ci++) {
        // 6x6 input patch -> registers (float2 LDS, even offsets guaranteed)
        float in[6][6];
        const float* xb = x_s + ci*324 + sy*18 + sx;
        #pragma unroll
        for (int i = 0; i < 6; i++) {
            const float2* p = reinterpret_cast<const float2*>(xb + i*18);
            const float2 a = p[0], b = p[1], c = p[2];
            in[i][0]=a.x; in[i][1]=a.y; in[i][2]=b.x;
            in[i][3]=b.y; in[i][4]=c.x; in[i][5]=c.y;
        }
        // 9 taps x 2 couts as float2
        const float2* wp = reinterpret_cast<const float2*>(w_s + ci*288 + 2*cop);
        #pragma unroll
        for (int kh = 0; kh < 3; kh++) {
            #pragma unroll
            for (int kw = 0; kw < 3; kw++) {
                const float2 wv = wp[(kh*3 + kw) * 16];
                #pragma unroll
                for (int i = 0; i < 4; i++) {
                    #pragma unroll
                    for (int j = 0; j < 4; j++) {
                        const float xv = in[i+kh][j+kw];
                        acc0[i*4+j] = fmaf(xv, wv.x, acc0[i*4+j]);
                        acc1[i*4+j] = fmaf(xv, wv.y, acc1[i*4+j]);
                    }
                }
            }
        }
    }

    // epilogue: add bias, float4 stores (16B aligned: x offset multiple of 4)
    const int co0 = 2*cop;
    const float b0 = g_bias[n*COUT + co0];
    const float b1 = g_bias[n*COUT + co0 + 1];
    const int oy = ty*16 + sy, ox = tx*16 + sx;
    float* o0 = out + (((size_t)n*COUT + co0)*HW + oy)*HW + ox;
    float* o1 = o0 + (size_t)HW*HW;
    #pragma unroll
    for (int i = 0; i < 4; i++) {
        float4 v0 = make_float4(acc0[i*4+0]+b0, acc0[i*4+1]+b0,
                                acc0[i*4+2]+b0, acc0[i*4+3]+b0);
        float4 v1 = make_float4(acc1[i*4+0]+b1, acc1[i*4+1]+b1,
                                acc1[i*4+2]+b1, acc1[i*4+3]+b1);
        *reinterpret_cast<float4*>(o0 + i*HW) = v0;
        *reinterpret_cast<float4*>(o1 + i*HW) = v1;
    }
}

// ---------------------------------------------------------------------------
extern "C" void kernel_launch(void* const* d_in, const int* in_sizes, int n_in,
                              void* d_out, int out_size)
{
    const float* x      = (const float*)d_in[0];
    const float* y      = (const float*)d_in[1];
    const float* weight = (const float*)d_in[2];
    const float* fc_w1  = (const float*)d_in[3];
    const float* fc_b1  = (const float*)d_in[4];
    const float* fc_a   = (const float*)d_in[5];
    const float* fc_w2  = (const float*)d_in[6];
    const float* fc_b2  = (const float*)d_in[7];
    const float* b_w1   = (const float*)d_in[8];
    const float* b_b1   = (const float*)d_in[9];
    const float* b_a    = (const float*)d_in[10];
    const float* b_w2   = (const float*)d_in[11];
    const float* b_b2   = (const float*)d_in[12];
    float* out = (float*)d_out;

    cudaFuncSetAttribute(conv_kernel,
                         cudaFuncAttributeMaxDynamicSharedMemorySize,
                         CONV_SMEM_BYTES);

    mlp_kernel<<<dim3(BN, 13), 256>>>(y, weight,
                                      fc_w1, fc_b1, fc_a, fc_w2, fc_b2,
                                      b_w1, b_b1, b_a, b_w2, b_b2);

    conv_kernel<<<dim3(HW/16, HW/16, BN), 256, CONV_SMEM_BYTES>>>(x, out);
}

// round 2
// speedup vs baseline: 1.2355x; 1.2355x over previous
#include <cuda_runtime.h>
#include <math.h>

#define BN   8
#define CIN  32
#define COUT 32
#define HW   384
#define AUX  128
#define HID  256
#define MODOUT (COUT*CIN*9)   // 9216

// Scratch (allocation-free rule: __device__ globals)
__device__ float g_wmod[BN * MODOUT];   // layout [n][ci][k][co]  (co minor!)
__device__ float g_bias[BN * COUT];
__device__ float g_h[BN * 2 * HID];     // hidden activations, [n][branch][HID]

// ---------------------------------------------------------------------------
// packed f32x2 helpers (FFMA2 — 2 fp32 FMAs per issue slot, PTX-only path)
// ---------------------------------------------------------------------------
__device__ __forceinline__ unsigned long long ffma2(unsigned long long a,
                                                    unsigned long long b,
                                                    unsigned long long c) {
    unsigned long long d;
    asm("fma.rn.f32x2 %0, %1, %2, %3;" : "=l"(d) : "l"(a), "l"(b), "l"(c));
    return d;
}
__device__ __forceinline__ unsigned long long pack2(float x) {
    unsigned long long d;
    asm("mov.b64 %0, {%1, %1};" : "=l"(d) : "f"(x));
    return d;
}
__device__ __forceinline__ void unpack2(unsigned long long v, float& lo, float& hi) {
    asm("mov.b64 {%0, %1}, %2;" : "=f"(lo), "=f"(hi) : "l"(v));
}

// ---------------------------------------------------------------------------
// MLP kernel 1: hidden layers for both branches.  grid=(8,2), block=256.
// ---------------------------------------------------------------------------
__global__ void mlp1_kernel(const float* __restrict__ y,
                            const float* __restrict__ fc_w1, const float* __restrict__ fc_b1,
                            const float* __restrict__ fc_a_p,
                            const float* __restrict__ b_w1,  const float* __restrict__ b_b1,
                            const float* __restrict__ b_a_p)
{
    __shared__ float y_s[AUX];
    const int n  = blockIdx.x;
    const int br = blockIdx.y;          // 0 = modulation, 1 = bias
    const int t  = threadIdx.x;

    if (t < AUX) y_s[t] = y[n*AUX + t];
    __syncthreads();

    const float* w1 = br ? b_w1 : fc_w1;
    const float* b1 = br ? b_b1 : fc_b1;
    const float  a  = br ? *b_a_p : *fc_a_p;

    float h0 = 0.f, h1 = 0.f, h2 = 0.f, h3 = 0.f;
    #pragma unroll
    for (int i = 0; i < AUX; i += 4) {
        h0 = fmaf(y_s[i+0], w1[(i+0)*HID + t], h0);
        h1 = fmaf(y_s[i+1], w1[(i+1)*HID + t], h1);
        h2 = fmaf(y_s[i+2], w1[(i+2)*HID + t], h2);
        h3 = fmaf(y_s[i+3], w1[(i+3)*HID + t], h3);
    }
    const float h = (h0 + h1) + (h2 + h3) + b1[t];
    g_h[(n*2 + br)*HID + t] = (h >= 0.f) ? h : a*h;
}

// ---------------------------------------------------------------------------
// MLP kernel 2: output layers. grid=289: blocks 0..287 mod GEMM (8n x 36 chunks
// of 256 outputs), block 288 = all 8x32 biases.
// ---------------------------------------------------------------------------
__global__ void mlp2_kernel(const float* __restrict__ weight,
                            const float* __restrict__ fc_w2, const float* __restrict__ fc_b2,
                            const float* __restrict__ b_w2,  const float* __restrict__ b_b2)
{
    __shared__ float h_s[BN * HID];     // bias block needs all 8; mod uses 256
    const int t = threadIdx.x;

    if (blockIdx.x < 288) {
        // ---- modulation outputs ----
        const int n  = blockIdx.x / 36;
        const int jb = (blockIdx.x % 36) * 256;
        h_s[t] = g_h[n*2*HID + t];
        __syncthreads();

        const int j = jb + t;           // j = co*288 + ci*9 + k
        float m0 = 0.f, m1 = 0.f, m2 = 0.f, m3 = 0.f;
        #pragma unroll
        for (int hh = 0; hh < HID; hh += 4) {
            m0 = fmaf(h_s[hh+0], fc_w2[(hh+0)*MODOUT + j], m0);
            m1 = fmaf(h_s[hh+1], fc_w2[(hh+1)*MODOUT + j], m1);
            m2 = fmaf(h_s[hh+2], fc_w2[(hh+2)*MODOUT + j], m2);
            m3 = fmaf(h_s[hh+3], fc_w2[(hh+3)*MODOUT + j], m3);
        }
        const float m  = (m0 + m1) + (m2 + m3) + fc_b2[j];
        const float sg = 1.f / (1.f + expf(-m));
        const float wm = sg * weight[j];
        const int co = j / 288;
        const int r  = j - co*288;      // ci*9 + k
        g_wmod[n*MODOUT + r*32 + co] = wm;   // transpose to co-minor
    } else {
        // ---- bias outputs (all 8 samples, 32 couts) ----
        #pragma unroll
        for (int idx = t; idx < BN*HID; idx += 256)
            h_s[idx] = g_h[((idx >> 8)*2 + 1)*HID + (idx & 255)];
        __syncthreads();

        const int n  = t >> 5;
        const int co = t & 31;
        const float* hb = h_s + n*HID;
        float m0 = 0.f, m1 = 0.f, m2 = 0.f, m3 = 0.f;
        #pragma unroll
        for (int hh = 0; hh < HID; hh += 4) {
            m0 = fmaf(hb[hh+0], b_w2[(hh+0)*COUT + co], m0);
            m1 = fmaf(hb[hh+1], b_w2[(hh+1)*COUT + co], m1);
            m2 = fmaf(hb[hh+2], b_w2[(hh+2)*COUT + co], m2);
            m3 = fmaf(hb[hh+3], b_w2[(hh+3)*COUT + co], m3);
        }
        g_bias[n*COUT + co] = (m0 + m1) + (m2 + m3) + b_b2[co];
    }
}

// ---------------------------------------------------------------------------
// Conv kernel: per-sample direct 3x3, pad 1, FFMA2 over cout pairs.
// Block: one sample, all 32 couts, 16x16 output tile.
// smem: weights [ci][k][co] 9216 f + input tile [ci][18][18] 10368 f.
// Thread: couts {2cop,2cop+1} packed in f32x2, 4x4 spatial micro-tile.
// ---------------------------------------------------------------------------
#define CONV_SMEM_BYTES ((9216 + 10368) * 4)

__global__ __launch_bounds__(256, 2)
void conv_kernel(const float* __restrict__ x, float* __restrict__ out)
{
    extern __shared__ float smem[];
    float* w_s = smem;            // 9216  floats: (ci*9+k)*32 + co
    float* x_s = smem + 9216;     // 10368 floats: ci*324 + ly*18 + lx

    const int n  = blockIdx.z;
    const int ty = blockIdx.y, tx = blockIdx.x;
    const int tid = threadIdx.x;

    const float* wsrc = g_wmod + n*MODOUT;
    #pragma unroll
    for (int i = tid; i < MODOUT; i += 256) w_s[i] = wsrc[i];

    const float* xn = x + (size_t)n * CIN * HW * HW;
    const int y0 = ty*16 - 1, x0 = tx*16 - 1;
    for (int i = tid; i < CIN*18*18; i += 256) {
        const int ci = i / 324;
        const int r  = i - ci*324;
        const int ly = r / 18, lx = r - ly*18;
        const int gy = y0 + ly, gx = x0 + lx;
        float v = 0.f;
        if ((unsigned)gy < HW && (unsigned)gx < HW)
            v = xn[(ci*HW + gy)*HW + gx];
        x_s[i] = v;
    }
    __syncthreads();

    const int cop = tid & 15;          // cout pair -> couts {2cop, 2cop+1}
    const int s   = tid >> 4;          // spatial micro-tile 0..15
    const int sy  = (s >> 2) * 4;
    const int sx  = (s & 3) * 4;

    unsigned long long acc[16];
    const unsigned long long zz = pack2(0.f);
    #pragma unroll
    for (int i = 0; i < 16; i++) acc[i] = zz;

    #pragma unroll 1
    for (int ci = 0; ci < CIN; ci++) {
        // 9 weight pairs for this (ci, cout-pair): already packed in smem
        const unsigned long long* wp =
            reinterpret_cast<const unsigned long long*>(w_s + ci*288) + cop;
        unsigned long long w[9];
        #pragma unroll
        for (int k = 0; k < 9; k++) w[k] = wp[k*16];

        const float* xb = x_s + ci*324 + sy*18 + sx;
        #pragma unroll
        for (int r = 0; r < 6; r++) {
            const float2* p = reinterpret_cast<const float2*>(xb + r*18);
            const float2 a = p[0], b = p[1], c = p[2];
            unsigned long long xp[6];
            xp[0] = pack2(a.x); xp[1] = pack2(a.y);
            xp[2] = pack2(b.x); xp[3] = pack2(b.y);
            xp[4] = pack2(c.x); xp[5] = pack2(c.y);
            // input row r feeds output rows i with kh = r-i, 0<=kh<=2
            #pragma unroll
            for (int i = 0; i < 4; i++) {
                if (r >= i && r <= i + 2) {
                    const int kh = r - i;
                    #pragma unroll
                    for (int kw = 0; kw < 3; kw++) {
                        #pragma unroll
                        for (int j = 0; j < 4; j++)
                            acc[i*4+j] = ffma2(xp[j+kw], w[kh*3+kw], acc[i*4+j]);
                    }
                }
            }
        }
    }

    // epilogue
    const int co0 = 2*cop;
    const float b0 = g_bias[n*COUT + co0];
    const float b1 = g_bias[n*COUT + co0 + 1];
    const int oy = ty*16 + sy, ox = tx*16 + sx;
    float* o0 = out + (((size_t)n*COUT + co0)*HW + oy)*HW + ox;
    float* o1 = o0 + (size_t)HW*HW;
    #pragma unroll
    for (int i = 0; i < 4; i++) {
        float v0[4], v1[4];
        #pragma unroll
        for (int j = 0; j < 4; j++) {
            float lo, hi;
            unpack2(acc[i*4+j], lo, hi);
            v0[j] = lo + b0;
            v1[j] = hi + b1;
        }
        *reinterpret_cast<float4*>(o0 + i*HW) = make_float4(v0[0],v0[1],v0[2],v0[3]);
        *reinterpret_cast<float4*>(o1 + i*HW) = make_float4(v1[0],v1[1],v1[2],v1[3]);
    }
}

// ---------------------------------------------------------------------------
extern "C" void kernel_launch(void* const* d_in, const int* in_sizes, int n_in,
                              void* d_out, int out_size)
{
    const float* x      = (const float*)d_in[0];
    const float* y      = (const float*)d_in[1];
    const float* weight = (const float*)d_in[2];
    const float* fc_w1  = (const float*)d_in[3];
    const float* fc_b1  = (const float*)d_in[4];
    const float* fc_a   = (const float*)d_in[5];
    const float* fc_w2  = (const float*)d_in[6];
    const float* fc_b2  = (const float*)d_in[7];
    const float* b_w1   = (const float*)d_in[8];
    const float* b_b1   = (const float*)d_in[9];
    const float* b_a    = (const float*)d_in[10];
    const float* b_w2   = (const float*)d_in[11];
    const float* b_b2   = (const float*)d_in[12];
    float* out = (float*)d_out;

    cudaFuncSetAttribute(conv_kernel,
                         cudaFuncAttributeMaxDynamicSharedMemorySize,
                         CONV_SMEM_BYTES);

    mlp1_kernel<<<dim3(BN, 2), 256>>>(y, fc_w1, fc_b1, fc_a, b_w1, b_b1, b_a);
    mlp2_kernel<<<289, 256>>>(weight, fc_w2, fc_b2, b_w2, b_b2);
    conv_kernel<<<dim3(HW/16, HW/16, BN), 256, CONV_SMEM_BYTES>>>(x, out);
}

// round 4
// speedup vs baseline: 1.5406x; 1.2469x over previous
#include <cuda_runtime.h>
#include <cuda_bf16.h>
#include <math.h>
#include <stdint.h>

#define BN   8
#define CIN  32
#define COUT 32
#define HW   384
#define AUX  128
#define HID  256
#define MODOUT (COUT*CIN*9)   // 9216
#define KDIM 288              // tap*32 + ci
#define WST  296              // padded W row stride (conflict-free ldmatrix)

// Scratch (allocation-free rule: __device__ globals)
__device__ float g_bias[BN * COUT];
__device__ float g_h[BN * 2 * HID];
__device__ __nv_bfloat16 g_wh[BN * COUT * KDIM];  // [n][co][tap*32+ci] hi
__device__ __nv_bfloat16 g_wl[BN * COUT * KDIM];  // lo

// ---------------------------------------------------------------------------
// warp-MMA helpers (sm_80-class, valid on compute_103 without 'a')
// ---------------------------------------------------------------------------
__device__ __forceinline__ uint32_t smem_u32(const void* p) {
    uint32_t a;
    asm("{ .reg .u64 t; cvta.to.shared.u64 t, %1; cvt.u32.u64 %0, t; }"
        : "=r"(a) : "l"(p));
    return a;
}
__device__ __forceinline__ void ldm4(uint32_t r[4], uint32_t addr) {
    asm volatile("ldmatrix.sync.aligned.m8n8.x4.shared.b16 {%0,%1,%2,%3}, [%4];"
        : "=r"(r[0]), "=r"(r[1]), "=r"(r[2]), "=r"(r[3]) : "r"(addr));
}
__device__ __forceinline__ void mma_bf16(float d[4], const uint32_t a[4],
                                         const uint32_t b[2]) {
    asm volatile("mma.sync.aligned.m16n8k16.row.col.f32.bf16.bf16.f32 "
        "{%0,%1,%2,%3}, {%4,%5,%6,%7}, {%8,%9}, {%0,%1,%2,%3};"
        : "+f"(d[0]), "+f"(d[1]), "+f"(d[2]), "+f"(d[3])
        : "r"(a[0]), "r"(a[1]), "r"(a[2]), "r"(a[3]), "r"(b[0]), "r"(b[1]));
}

// ---------------------------------------------------------------------------
// MLP kernel 1: hidden layers for both branches.  grid=(8,2), block=256.
// ---------------------------------------------------------------------------
__global__ void mlp1_kernel(const float* __restrict__ y,
                            const float* __restrict__ fc_w1, const float* __restrict__ fc_b1,
                            const float* __restrict__ fc_a_p,
                            const float* __restrict__ b_w1,  const float* __restrict__ b_b1,
                            const float* __restrict__ b_a_p)
{
    __shared__ float y_s[AUX];
    const int n  = blockIdx.x;
    const int br = blockIdx.y;
    const int t  = threadIdx.x;

    if (t < AUX) y_s[t] = y[n*AUX + t];
    __syncthreads();

    const float* w1 = br ? b_w1 : fc_w1;
    const float* b1 = br ? b_b1 : fc_b1;
    const float  a  = br ? *b_a_p : *fc_a_p;

    float acc[8] = {0,0,0,0,0,0,0,0};
    #pragma unroll
    for (int i = 0; i < AUX; i += 8) {
        #pragma unroll
        for (int q = 0; q < 8; q++)
            acc[q] = fmaf(y_s[i+q], w1[(i+q)*HID + t], acc[q]);
    }
    const float h = ((acc[0]+acc[1])+(acc[2]+acc[3]))
                  + ((acc[4]+acc[5])+(acc[6]+acc[7])) + b1[t];
    g_h[(n*2 + br)*HID + t] = (h >= 0.f) ? h : a*h;
}

// ---------------------------------------------------------------------------
// MLP kernel 2: output layers -> bf16 hi/lo modulated weights + bias.
// ---------------------------------------------------------------------------
__global__ void mlp2_kernel(const float* __restrict__ weight,
                            const float* __restrict__ fc_w2, const float* __restrict__ fc_b2,
                            const float* __restrict__ b_w2,  const float* __restrict__ b_b2)
{
    __shared__ float h_s[BN * HID];
    const int t = threadIdx.x;

    if (blockIdx.x < 288) {
        const int n  = blockIdx.x / 36;
        const int jb = (blockIdx.x % 36) * 256;
        h_s[t] = g_h[n*2*HID + t];
        __syncthreads();

        const int j = jb + t;           // j = co*288 + ci*9 + tap
        float m0 = 0.f, m1 = 0.f, m2 = 0.f, m3 = 0.f;
        #pragma unroll 4
        for (int hh = 0; hh < HID; hh += 4) {
            m0 = fmaf(h_s[hh+0], fc_w2[(hh+0)*MODOUT + j], m0);
            m1 = fmaf(h_s[hh+1], fc_w2[(hh+1)*MODOUT + j], m1);
            m2 = fmaf(h_s[hh+2], fc_w2[(hh+2)*MODOUT + j], m2);
            m3 = fmaf(h_s[hh+3], fc_w2[(hh+3)*MODOUT + j], m3);
        }
        const float mm = (m0 + m1) + (m2 + m3) + fc_b2[j];
        const float sg = 1.f / (1.f + expf(-mm));
        const float wm = sg * weight[j];
        const int co  = j / 288;
        const int r   = j - co*288;
        const int ci  = r / 9;
        const int tap = r - ci*9;
        __nv_bfloat16 hi = __float2bfloat16(wm);
        __nv_bfloat16 lo = __float2bfloat16(wm - __bfloat162float(hi));
        const int o = (n*COUT + co)*KDIM + tap*32 + ci;
        g_wh[o] = hi;
        g_wl[o] = lo;
    } else {
        #pragma unroll
        for (int idx = t; idx < BN*HID; idx += 256)
            h_s[idx] = g_h[((idx >> 8)*2 + 1)*HID + (idx & 255)];
        __syncthreads();

        const int n  = t >> 5;
        const int co = t & 31;
        const float* hb = h_s + n*HID;
        float m0 = 0.f, m1 = 0.f, m2 = 0.f, m3 = 0.f;
        #pragma unroll 4
        for (int hh = 0; hh < HID; hh += 4) {
            m0 = fmaf(hb[hh+0], b_w2[(hh+0)*COUT + co], m0);
            m1 = fmaf(hb[hh+1], b_w2[(hh+1)*COUT + co], m1);
            m2 = fmaf(hb[hh+2], b_w2[(hh+2)*COUT + co], m2);
            m3 = fmaf(hb[hh+3], b_w2[(hh+3)*COUT + co], m3);
        }
        g_bias[n*COUT + co] = (m0 + m1) + (m2 + m3) + b_b2[co];
    }
}

// ---------------------------------------------------------------------------
// Conv: warp-level implicit GEMM (mma.sync bf16, 3-pass hi/lo split).
// CTA = 1 sample x 128-pixel row chunk x 32 couts; 12 rows per CTA.
// M = 32 couts (A = weights via ldmatrix), N = 16 pixels/warp (B built via LDS),
// K = 288 (k = tap*32 + ci), rolling 3-row input slab (bf16 hi/lo) in smem.
// ---------------------------------------------------------------------------
#define RP       132
#define W_BYTES  (COUT*WST*2)            // 18944 per slab
#define SLAB_B   (CIN*3*RP*2)            // 25344 per slab
#define OFF_WH   0
#define OFF_WL   (W_BYTES)               // 18944
#define OFF_XH   (2*W_BYTES)             // 37888
#define OFF_XL   (2*W_BYTES + SLAB_B)    // 63232
#define OFF_BIAS (2*W_BYTES + 2*SLAB_B)  // 88576
#define CONV_SMEM (OFF_BIAS + 128)       // 88704 -> 2 CTAs/SM

__device__ __forceinline__ void stage_row(const float* __restrict__ xn,
                                          uint16_t* __restrict__ xh,
                                          uint16_t* __restrict__ xl,
                                          int gy, int x0, int tid)
{
    const int slot = ((gy % 3) + 3) % 3;
    for (int i = tid; i < CIN*RP; i += 256) {
        const int ci = i / RP;
        const int c  = i - ci*RP;
        const int gx = x0 - 1 + c;
        float v = 0.f;
        if (c < 130 && (unsigned)gy < (unsigned)HW && (unsigned)gx < (unsigned)HW)
            v = xn[(ci*HW + gy)*HW + gx];
        __nv_bfloat16 h = __float2bfloat16(v);
        __nv_bfloat16 l = __float2bfloat16(v - __bfloat162float(h));
        const int idx = (ci*3 + slot)*RP + c;
        xh[idx] = *reinterpret_cast<unsigned short*>(&h);
        xl[idx] = *reinterpret_cast<unsigned short*>(&l);
    }
}

__global__ void __launch_bounds__(256, 2)
conv_mma(const float* __restrict__ x, float* __restrict__ out)
{
    extern __shared__ char smem[];
    uint16_t* xh  = reinterpret_cast<uint16_t*>(smem + OFF_XH);
    uint16_t* xl  = reinterpret_cast<uint16_t*>(smem + OFF_XL);
    float* bias_s = reinterpret_cast<float*>(smem + OFF_BIAS);

    const int tid  = threadIdx.x;
    const int lane = tid & 31;
    const int w    = tid >> 5;
    const int n    = blockIdx.y;
    const int rid  = blockIdx.x;
    const int x0   = (rid % 3) * 128;
    const int row0 = (rid / 3) * 12;

    // ---- load per-sample weights into padded smem rows ----
    {
        const uint16_t* gh = reinterpret_cast<const uint16_t*>(g_wh) + (size_t)n*MODOUT;
        const uint16_t* gl = reinterpret_cast<const uint16_t*>(g_wl) + (size_t)n*MODOUT;
        uint16_t* whs = reinterpret_cast<uint16_t*>(smem + OFF_WH);
        uint16_t* wls = reinterpret_cast<uint16_t*>(smem + OFF_WL);
        for (int i = tid; i < COUT*KDIM; i += 256) {
            const int co = i / KDIM, k = i - co*KDIM;
            whs[co*WST + k] = gh[i];
            wls[co*WST + k] = gl[i];
        }
        if (tid < COUT) bias_s[tid] = g_bias[n*COUT + tid];
    }

    const float* xn = x + (size_t)n * CIN * HW * HW;
    stage_row(xn, xh, xl, row0 - 1, x0, tid);
    stage_row(xn, xh, xl, row0,     x0, tid);
    stage_row(xn, xh, xl, row0 + 1, x0, tid);
    __syncthreads();

    const uint32_t sb   = smem_u32(smem);
    const uint32_t aoff = (uint32_t)(((lane & 15)*WST + ((lane >> 4) << 3)) * 2);
    const uint32_t whb  = sb + OFF_WH + aoff;
    const uint32_t wlb  = sb + OFF_WL + aoff;
    const int p0 = w * 16;

    #pragma unroll 1
    for (int t = 0; t < 12; t++) {
        const int y = row0 + t;
        const int sr0 = (y + 2) % 3;       // slot of row y-1
        const int sr1 =  y      % 3;       // slot of row y
        const int sr2 = (y + 1) % 3;       // slot of row y+1

        float d[2][2][4];
        #pragma unroll
        for (int mi = 0; mi < 2; mi++)
            #pragma unroll
            for (int j = 0; j < 2; j++)
                #pragma unroll
                for (int q = 0; q < 4; q++) d[mi][j][q] = 0.f;

        #pragma unroll
        for (int tap = 0; tap < 9; tap++) {
            const int kh = tap / 3, kw = tap - kh*3;
            const int slot = (kh == 0) ? sr0 : (kh == 1) ? sr1 : sr2;
            const int rowoff = slot*RP + kw + p0 + (lane >> 2);
            #pragma unroll
            for (int half = 0; half < 2; half++) {
                const int c = tap*2 + half;
                uint32_t a0[4], a1[4], l0[4], l1[4];
                ldm4(a0, whb + c*32);
                ldm4(a1, whb + c*32 + 16*WST*2);
                ldm4(l0, wlb + c*32);
                ldm4(l1, wlb + c*32 + 16*WST*2);
                const int ci_a = half*16 + (lane & 3)*2;
                const int ob = ci_a*(3*RP) + rowoff;
                #pragma unroll
                for (int j = 0; j < 2; j++) {
                    const int o = ob + 8*j;
                    uint32_t bh[2], bl[2];
                    bh[0] = (uint32_t)xh[o]          | ((uint32_t)xh[o +   3*RP] << 16);
                    bh[1] = (uint32_t)xh[o + 24*RP]  | ((uint32_t)xh[o +  27*RP] << 16);
                    bl[0] = (uint32_t)xl[o]          | ((uint32_t)xl[o +   3*RP] << 16);
                    bl[1] = (uint32_t)xl[o + 24*RP]  | ((uint32_t)xl[o +  27*RP] << 16);
                    mma_bf16(d[0][j], a0, bh);       // Wh * xh
                    mma_bf16(d[1][j], a1, bh);
                    mma_bf16(d[0][j], l0, bh);       // Wl * xh
                    mma_bf16(d[1][j], l1, bh);
                    mma_bf16(d[0][j], a0, bl);       // Wh * xl
                    mma_bf16(d[1][j], a1, bl);
                }
            }
        }

        // ---- epilogue: bias + coalesced float2 stores ----
        const int pxb = x0 + p0 + (lane & 3)*2;
        #pragma unroll
        for (int mi = 0; mi < 2; mi++) {
            const int co = mi*16 + (lane >> 2);
            const float b0 = bias_s[co];
            const float b1 = bias_s[co + 8];
            #pragma unroll
            for (int j = 0; j < 2; j++) {
                float* op = out + (((size_t)n*COUT + co)*HW + y)*HW + pxb + 8*j;
                *reinterpret_cast<float2*>(op) =
                    make_float2(d[mi][j][0] + b0, d[mi][j][1] + b0);
                *reinterpret_cast<float2*>(op + (size_t)8*HW*HW) =
                    make_float2(d[mi][j][2] + b1, d[mi][j][3] + b1);
            }
        }

        __syncthreads();
        if (t < 11) stage_row(xn, xh, xl, y + 2, x0, tid);
        __syncthreads();
    }
}

// ---------------------------------------------------------------------------
extern "C" void kernel_launch(void* const* d_in, const int* in_sizes, int n_in,
                              void* d_out, int out_size)
{
    const float* x      = (const float*)d_in[0];
    const float* y      = (const float*)d_in[1];
    const float* weight = (const float*)d_in[2];
    const float* fc_w1  = (const float*)d_in[3];
    const float* fc_b1  = (const float*)d_in[4];
    const float* fc_a   = (const float*)d_in[5];
    const float* fc_w2  = (const float*)d_in[6];
    const float* fc_b2  = (const float*)d_in[7];
    const float* b_w1   = (const float*)d_in[8];
    const float* b_b1   = (const float*)d_in[9];
    const float* b_a    = (const float*)d_in[10];
    const float* b_w2   = (const float*)d_in[11];
    const float* b_b2   = (const float*)d_in[12];
    float* out = (float*)d_out;

    cudaFuncSetAttribute(conv_mma,
                         cudaFuncAttributeMaxDynamicSharedMemorySize,
                         CONV_SMEM);

    mlp1_kernel<<<dim3(BN, 2), 256>>>(y, fc_w1, fc_b1, fc_a, b_w1, b_b1, b_a);
    mlp2_kernel<<<289, 256>>>(weight, fc_w2, fc_b2, b_w2, b_b2);
    conv_mma<<<dim3(96, BN), 256, CONV_SMEM>>>(x, out);
}

// round 5
// speedup vs baseline: 1.8491x; 1.2003x over previous
#include <cuda_runtime.h>
#include <cuda_bf16.h>
#include <math.h>
#include <stdint.h>

#define BN   8
#define CIN  32
#define COUT 32
#define HW   384
#define AUX  128
#define HID  256
#define MODOUT (COUT*CIN*9)   // 9216
#define KDIM 288              // tap*32 + ci
#define WST  296              // padded W row stride (conflict-free ldmatrix)

// Scratch (allocation-free rule: __device__ globals)
__device__ float g_bias[BN * COUT];
__device__ __nv_bfloat16 g_wh[BN * COUT * KDIM];  // [n][co][tap*32+ci] hi
__device__ __nv_bfloat16 g_wl[BN * COUT * KDIM];  // lo

// ---------------------------------------------------------------------------
// warp-MMA helpers (sm_80-class, valid on compute_103 without 'a')
// ---------------------------------------------------------------------------
__device__ __forceinline__ uint32_t smem_u32(const void* p) {
    uint32_t a;
    asm("{ .reg .u64 t; cvta.to.shared.u64 t, %1; cvt.u32.u64 %0, t; }"
        : "=r"(a) : "l"(p));
    return a;
}
__device__ __forceinline__ void ldm4(uint32_t r[4], uint32_t addr) {
    asm volatile("ldmatrix.sync.aligned.m8n8.x4.shared.b16 {%0,%1,%2,%3}, [%4];"
        : "=r"(r[0]), "=r"(r[1]), "=r"(r[2]), "=r"(r[3]) : "r"(addr));
}
__device__ __forceinline__ void mma_bf16(float d[4], const uint32_t a[4],
                                         const uint32_t b[2]) {
    asm volatile("mma.sync.aligned.m16n8k16.row.col.f32.bf16.bf16.f32 "
        "{%0,%1,%2,%3}, {%4,%5,%6,%7}, {%8,%9}, {%0,%1,%2,%3};"
        : "+f"(d[0]), "+f"(d[1]), "+f"(d[2]), "+f"(d[3])
        : "r"(a[0]), "r"(a[1]), "r"(a[2]), "r"(a[3]), "r"(b[0]), "r"(b[1]));
}

// ---------------------------------------------------------------------------
// Fused MLP kernel: grid 289.
// Blocks 0..287: recompute mod hidden for their sample, then 256 mod outputs.
// Block 288: recompute bias hidden for all 8 samples, then all 8x32 biases.
// ---------------------------------------------------------------------------
__global__ void mlp_fused(const float* __restrict__ y,
                          const float* __restrict__ weight,
                          const float* __restrict__ fc_w1, const float* __restrict__ fc_b1,
                          const float* __restrict__ fc_a_p,
                          const float* __restrict__ fc_w2, const float* __restrict__ fc_b2,
                          const float* __restrict__ b_w1,  const float* __restrict__ b_b1,
                          const float* __restrict__ b_a_p,
                          const float* __restrict__ b_w2,  const float* __restrict__ b_b2)
{
    __shared__ float y_s[BN * AUX];
    __shared__ float h_s[BN * HID];
    const int t = threadIdx.x;

    if (blockIdx.x < 288) {
        const int n  = blockIdx.x / 36;
        const int jb = (blockIdx.x % 36) * 256;

        if (t < AUX) y_s[t] = y[n*AUX + t];
        __syncthreads();

        // hidden layer (thread t -> h[t])
        {
            const float a = *fc_a_p;
            float acc[8] = {0,0,0,0,0,0,0,0};
            #pragma unroll
            for (int i = 0; i < AUX; i += 8) {
                #pragma unroll
                for (int q = 0; q < 8; q++)
                    acc[q] = fmaf(y_s[i+q], fc_w1[(i+q)*HID + t], acc[q]);
            }
            const float h = ((acc[0]+acc[1])+(acc[2]+acc[3]))
                          + ((acc[4]+acc[5])+(acc[6]+acc[7])) + fc_b1[t];
            h_s[t] = (h >= 0.f) ? h : a*h;
        }
        __syncthreads();

        const int j = jb + t;           // j = co*288 + ci*9 + tap
        float m0 = 0.f, m1 = 0.f, m2 = 0.f, m3 = 0.f;
        #pragma unroll 4
        for (int hh = 0; hh < HID; hh += 4) {
            m0 = fmaf(h_s[hh+0], fc_w2[(hh+0)*MODOUT + j], m0);
            m1 = fmaf(h_s[hh+1], fc_w2[(hh+1)*MODOUT + j], m1);
            m2 = fmaf(h_s[hh+2], fc_w2[(hh+2)*MODOUT + j], m2);
            m3 = fmaf(h_s[hh+3], fc_w2[(hh+3)*MODOUT + j], m3);
        }
        const float mm = (m0 + m1) + (m2 + m3) + fc_b2[j];
        const float sg = 1.f / (1.f + expf(-mm));
        const float wm = sg * weight[j];
        const int co  = j / 288;
        const int r   = j - co*288;
        const int ci  = r / 9;
        const int tap = r - ci*9;
        __nv_bfloat16 hi = __float2bfloat16(wm);
        __nv_bfloat16 lo = __float2bfloat16(wm - __bfloat162float(hi));
        const int o = (n*COUT + co)*KDIM + tap*32 + ci;
        g_wh[o] = hi;
        g_wl[o] = lo;
    } else {
        // bias branch
        #pragma unroll
        for (int i = t; i < BN*AUX; i += 256) y_s[i] = y[i];
        __syncthreads();

        const float a = *b_a_p;
        #pragma unroll 1
        for (int n = 0; n < BN; n++) {
            float acc[4] = {0,0,0,0};
            #pragma unroll
            for (int i = 0; i < AUX; i += 4) {
                #pragma unroll
                for (int q = 0; q < 4; q++)
                    acc[q] = fmaf(y_s[n*AUX + i+q], b_w1[(i+q)*HID + t], acc[q]);
            }
            const float h = (acc[0]+acc[1]) + (acc[2]+acc[3]) + b_b1[t];
            h_s[n*HID + t] = (h >= 0.f) ? h : a*h;
        }
        __syncthreads();

        const int n  = t >> 5;
        const int co = t & 31;
        const float* hb = h_s + n*HID;
        float m0 = 0.f, m1 = 0.f, m2 = 0.f, m3 = 0.f;
        #pragma unroll 4
        for (int hh = 0; hh < HID; hh += 4) {
            m0 = fmaf(hb[hh+0], b_w2[(hh+0)*COUT + co], m0);
            m1 = fmaf(hb[hh+1], b_w2[(hh+1)*COUT + co], m1);
            m2 = fmaf(hb[hh+2], b_w2[(hh+2)*COUT + co], m2);
            m3 = fmaf(hb[hh+3], b_w2[(hh+3)*COUT + co], m3);
        }
        g_bias[n*COUT + co] = (m0 + m1) + (m2 + m3) + b_b2[co];
    }
}

// ---------------------------------------------------------------------------
// Conv: warp-level implicit GEMM (mma.sync bf16, 3-pass hi/lo split).
// Input slab layout: [slot(3)][col(130)][ci padded to 40]  (bf16)
//   -> a k-pair {ci,ci+1} is one aligned LDS.b32, bank-conflict-free
//      (col stride = 80B = 20 words; (c*20+q) mod 32 covers all banks).
// ---------------------------------------------------------------------------
#define RC       130                      // cols per slab row (x0-1 .. x0+128)
#define CIP      40                       // padded ci stride (elems)
#define SLAB_E   (3*RC*CIP)               // 15600 elems
#define W_BYTES  (COUT*WST*2)             // 18944
#define OFF_WH   0
#define OFF_WL   (W_BYTES)                // 18944
#define OFF_XH   (2*W_BYTES)              // 37888
#define OFF_XL   (OFF_XH + SLAB_E*2)      // 69088
#define OFF_BIAS (OFF_XL + SLAB_E*2)      // 100288
#define CONV_SMEM (OFF_BIAS + 128)        // 100416 -> 2 CTAs/SM

__device__ __forceinline__ void stage_row(const float* __restrict__ xn,
                                          uint16_t* __restrict__ xh,
                                          uint16_t* __restrict__ xl,
                                          int gy, int x0, int tid)
{
    const int slot = ((gy % 3) + 3) % 3;
    const bool yok = (unsigned)gy < (unsigned)HW;
    for (int i = tid; i < CIN*RC; i += 256) {
        const int ci = i / RC;
        const int c  = i - ci*RC;
        const int gx = x0 - 1 + c;
        float v = 0.f;
        if (yok && (unsigned)gx < (unsigned)HW)
            v = xn[(ci*HW + gy)*HW + gx];
        __nv_bfloat16 h = __float2bfloat16(v);
        float hf = __bfloat162float(h);
        __nv_bfloat16 l = __float2bfloat16(v - hf);
        const int idx = (slot*RC + c)*CIP + ci;
        xh[idx] = *reinterpret_cast<unsigned short*>(&h);
        xl[idx] = *reinterpret_cast<unsigned short*>(&l);
    }
}

__global__ void __launch_bounds__(256, 2)
conv_mma(const float* __restrict__ x, float* __restrict__ out)
{
    extern __shared__ char smem[];
    uint16_t* xh  = reinterpret_cast<uint16_t*>(smem + OFF_XH);
    uint16_t* xl  = reinterpret_cast<uint16_t*>(smem + OFF_XL);
    float* bias_s = reinterpret_cast<float*>(smem + OFF_BIAS);

    const int tid  = threadIdx.x;
    const int lane = tid & 31;
    const int w    = tid >> 5;
    const int n    = blockIdx.y;
    const int rid  = blockIdx.x;
    const int x0   = (rid % 3) * 128;
    const int row0 = (rid / 3) * 12;

    // ---- load per-sample weights into padded smem rows ----
    {
        const uint16_t* gh = reinterpret_cast<const uint16_t*>(g_wh) + (size_t)n*MODOUT;
        const uint16_t* gl = reinterpret_cast<const uint16_t*>(g_wl) + (size_t)n*MODOUT;
        uint16_t* whs = reinterpret_cast<uint16_t*>(smem + OFF_WH);
        uint16_t* wls = reinterpret_cast<uint16_t*>(smem + OFF_WL);
        for (int i = tid; i < COUT*KDIM; i += 256) {
            const int co = i / KDIM, k = i - co*KDIM;
            whs[co*WST + k] = gh[i];
            wls[co*WST + k] = gl[i];
        }
        if (tid < COUT) bias_s[tid] = g_bias[n*COUT + tid];
    }

    const float* xn = x + (size_t)n * CIN * HW * HW;
    stage_row(xn, xh, xl, row0 - 1, x0, tid);
    stage_row(xn, xh, xl, row0,     x0, tid);
    stage_row(xn, xh, xl, row0 + 1, x0, tid);
    __syncthreads();

    const uint32_t sb   = smem_u32(smem);
    const uint32_t aoff = (uint32_t)(((lane & 15)*WST + ((lane >> 4) << 3)) * 2);
    const uint32_t whb  = sb + OFF_WH + aoff;
    const uint32_t wlb  = sb + OFF_WL + aoff;
    const int p0 = w * 16;
    const int colbase = p0 + (lane >> 2);          // per-thread column base

    #pragma unroll 1
    for (int t = 0; t < 12; t++) {
        const int y = row0 + t;
        const int sr0 = (y + 2) % 3;       // slot of row y-1
        const int sr1 =  y      % 3;       // slot of row y
        const int sr2 = (y + 1) % 3;       // slot of row y+1

        float d[2][2][4];
        #pragma unroll
        for (int mi = 0; mi < 2; mi++)
            #pragma unroll
            for (int j = 0; j < 2; j++)
                #pragma unroll
                for (int q = 0; q < 4; q++) d[mi][j][q] = 0.f;

        #pragma unroll
        for (int tap = 0; tap < 9; tap++) {
            const int kh = tap / 3, kw = tap - kh*3;
            const int slot = (kh == 0) ? sr0 : (kh == 1) ? sr1 : sr2;
            const int cb = (slot*RC + colbase + kw)*CIP;   // + ci later
            #pragma unroll
            for (int half = 0; half < 2; half++) {
                const int c = tap*2 + half;
                uint32_t a0[4], a1[4], l0[4], l1[4];
                ldm4(a0, whb + c*32);
                ldm4(a1, whb + c*32 + 16*WST*2);
                ldm4(l0, wlb + c*32);
                ldm4(l1, wlb + c*32 + 16*WST*2);
                const int ci_a = half*16 + (lane & 3)*2;
                #pragma unroll
                for (int j = 0; j < 2; j++) {
                    const int o = cb + 8*j*CIP + ci_a;
                    uint32_t bh[2], bl[2];
                    bh[0] = *reinterpret_cast<const uint32_t*>(xh + o);
                    bh[1] = *reinterpret_cast<const uint32_t*>(xh + o + 8);
                    bl[0] = *reinterpret_cast<const uint32_t*>(xl + o);
                    bl[1] = *reinterpret_cast<const uint32_t*>(xl + o + 8);
                    mma_bf16(d[0][j], a0, bh);       // Wh * xh
                    mma_bf16(d[1][j], a1, bh);
                    mma_bf16(d[0][j], l0, bh);       // Wl * xh
                    mma_bf16(d[1][j], l1, bh);
                    mma_bf16(d[0][j], a0, bl);       // Wh * xl
                    mma_bf16(d[1][j], a1, bl);
                }
            }
        }

        // ---- epilogue: bias + coalesced float2 stores ----
        const int pxb = x0 + p0 + (lane & 3)*2;
        #pragma unroll
        for (int mi = 0; mi < 2; mi++) {
            const int co = mi*16 + (lane >> 2);
            const float b0 = bias_s[co];
            const float b1 = bias_s[co + 8];
            #pragma unroll
            for (int j = 0; j < 2; j++) {
                float* op = out + (((size_t)n*COUT + co)*HW + y)*HW + pxb + 8*j;
                *reinterpret_cast<float2*>(op) =
                    make_float2(d[mi][j][0] + b0, d[mi][j][1] + b0);
                *reinterpret_cast<float2*>(op + (size_t)8*HW*HW) =
                    make_float2(d[mi][j][2] + b1, d[mi][j][3] + b1);
            }
        }

        __syncthreads();
        if (t < 11) stage_row(xn, xh, xl, y + 2, x0, tid);
        __syncthreads();
    }
}

// ---------------------------------------------------------------------------
extern "C" void kernel_launch(void* const* d_in, const int* in_sizes, int n_in,
                              void* d_out, int out_size)
{
    const float* x      = (const float*)d_in[0];
    const float* y      = (const float*)d_in[1];
    const float* weight = (const float*)d_in[2];
    const float* fc_w1  = (const float*)d_in[3];
    const float* fc_b1  = (const float*)d_in[4];
    const float* fc_a   = (const float*)d_in[5];
    const float* fc_w2  = (const float*)d_in[6];
    const float* fc_b2  = (const float*)d_in[7];
    const float* b_w1   = (const float*)d_in[8];
    const float* b_b1   = (const float*)d_in[9];
    const float* b_a    = (const float*)d_in[10];
    const float* b_w2   = (const float*)d_in[11];
    const float* b_b2   = (const float*)d_in[12];
    float* out = (float*)d_out;

    cudaFuncSetAttribute(conv_mma,
                         cudaFuncAttributeMaxDynamicSharedMemorySize,
                         CONV_SMEM);

    mlp_fused<<<289, 256>>>(y, weight, fc_w1, fc_b1, fc_a, fc_w2, fc_b2,
                            b_w1, b_b1, b_a, b_w2, b_b2);
    conv_mma<<<dim3(96, BN), 256, CONV_SMEM>>>(x, out);
}